// round 13
// baseline (speedup 1.0000x reference)
#include <cuda_runtime.h>
#include <cuda_fp16.h>
#include <cstdint>

#define NN 100000
#define DD 128
#define EE 600000
#define NT64 1563  // ceil(NN/64)

// ---------------- scratch (device globals: no runtime allocation) ----------------
__device__ float g_h[(size_t)NN * DD];
__device__ __half g_h16[(size_t)NN * DD];      // fp16 copy of h for the scatter gather
__device__ float g_agg[(size_t)NN * DD];       // scatter(h)
__device__ __half g_gi[(size_t)NN * 3 * DD];   // fp16 gate pre-activations
__device__ __half g_gh[(size_t)NN * 3 * DD];
__device__ float g_wf[3 * 384 * 128];          // Wfused[l] = Wih @ Wconv[l]
// pre-converted, pre-swizzled fp16 weights: 16 tiles of 128x128 (32KB blobs)
// tile order: W1 (0), Whh (1-3), W2 (4-6), Wfused (7-15)
__device__ __half g_wh[16 * 16384];

// ---------------- helpers ----------------
static __device__ __forceinline__ uint32_t smem_u32(const void* p) {
    uint32_t a;
    asm("{ .reg .u64 t; cvta.to.shared.u64 t, %1; cvt.u32.u64 %0, t; }" : "=r"(a) : "l"(p));
    return a;
}
static __device__ __forceinline__ void ldsm4(uint32_t* r, uint32_t addr) {
    asm volatile("ldmatrix.sync.aligned.m8n8.x4.shared.b16 {%0,%1,%2,%3}, [%4];"
                 : "=r"(r[0]), "=r"(r[1]), "=r"(r[2]), "=r"(r[3]) : "r"(addr));
}
// fp16 mma m16n8k16, fp32 accumulate in place
static __device__ __forceinline__ void mma16816(float* d, const uint32_t* a, const uint32_t* b) {
    asm volatile(
        "mma.sync.aligned.m16n8k16.row.col.f32.f16.f16.f32 "
        "{%0,%1,%2,%3}, {%4,%5,%6,%7}, {%8,%9}, {%0,%1,%2,%3};"
        : "+f"(d[0]), "+f"(d[1]), "+f"(d[2]), "+f"(d[3])
        : "r"(a[0]), "r"(a[1]), "r"(a[2]), "r"(a[3]), "r"(b[0]), "r"(b[1]));
}
static __device__ __forceinline__ void cpa16(uint32_t dst, const void* src) {
    asm volatile("cp.async.cg.shared.global [%0], [%1], 16;" :: "r"(dst), "l"(src) : "memory");
}
#define CP_COMMIT_WAIT() \
    asm volatile("cp.async.commit_group;\ncp.async.wait_group 0;" ::: "memory")

// swizzled byte offset within a tile (rows of 256B; 16B chunks XOR'd by row)
static __device__ __forceinline__ uint32_t swz(uint32_t r, uint32_t c2) {
    return r * 256 + (c2 ^ ((r & 7) << 4));
}

// Dekker split of 4 floats into fp16 hi/lo packed words (~22-bit effective mantissa)
static __device__ __forceinline__ void split4h(float4 v, uint2& hi, uint2& lo) {
    __half h0 = __float2half(v.x), h1 = __float2half(v.y);
    __half h2 = __float2half(v.z), h3 = __float2half(v.w);
    __half l0 = __float2half(v.x - __half2float(h0));
    __half l1 = __float2half(v.y - __half2float(h1));
    __half l2 = __float2half(v.z - __half2float(h2));
    __half l3 = __float2half(v.w - __half2float(h3));
    hi.x = (uint32_t)__half_as_ushort(h0) | ((uint32_t)__half_as_ushort(h1) << 16);
    hi.y = (uint32_t)__half_as_ushort(h2) | ((uint32_t)__half_as_ushort(h3) << 16);
    lo.x = (uint32_t)__half_as_ushort(l0) | ((uint32_t)__half_as_ushort(l1) << 16);
    lo.y = (uint32_t)__half_as_ushort(l2) | ((uint32_t)__half_as_ushort(l3) << 16);
}

static __device__ __forceinline__ float sigf(float x) { return 1.f / (1.f + __expf(-x)); }

// ---------------- prepass 1: Wfused[l] = Wih @ Wconv[l]  (fp32) ----------------
__global__ void wfused_kernel(const float* __restrict__ Wih, const float* __restrict__ Wconv) {
    int i = blockIdx.x * blockDim.x + threadIdx.x;  // 3*384*128
    if (i >= 3 * 384 * 128) return;
    int l = i / (384 * 128), r = (i >> 7) % 384, k = i & 127;
    const float* wc = Wconv + (size_t)l * 128 * 128;
    float s = 0.f;
#pragma unroll 8
    for (int j = 0; j < 128; j++) s = fmaf(__ldg(Wih + r * 128 + j), __ldg(wc + j * 128 + k), s);
    g_wf[i] = s;
}

// ---------------- prepass 2: convert + swizzle all 16 weight tiles to fp16 ----------------
// rows: [0,128) W1; [128,512) Whh; [512,896) W2; [896,2048) Wfused
__global__ void convert_w(const float* __restrict__ W1, const float* __restrict__ Whh,
                          const float* __restrict__ W2) {
    int i = blockIdx.x * blockDim.x + threadIdx.x;  // 2048*128 elements
    if (i >= 2048 * 128) return;
    int row = i >> 7, k = i & 127;
    float v;
    if (row < 128)       v = W1[(size_t)row * 128 + k];
    else if (row < 512)  v = Whh[(size_t)(row - 128) * 128 + k];
    else if (row < 896)  v = W2[(size_t)(row - 512) * 128 + k];
    else                 v = g_wf[(size_t)(row - 896) * 128 + k];
    int tile = row >> 7, tr = row & 127;
    uint32_t o = swz((uint32_t)tr, (uint32_t)(2 * k));
    *(__half*)((char*)g_wh + (size_t)tile * 32768 + o) = __float2half(v);
}

// SMEM: A hi/lo (64x128 = 16KB each), B (128x128 = 32KB) = 64KB -> occ 3
#define SM_A_HI 0
#define SM_A_LO 16384
#define SM_B 32768
#define SM_TOTAL 65536

// ======== mma.sync GEMM: C[N, MT*128] = act( A[N,128] @ W^T + b ) ========
// Tile 64(M) x 128(N); 8 warps = 2 row x 4 col, warp tile 32x32.
// 2-pass fp16 split: A_hi@B + A_lo@B (B single fp16).
// OUTH: 0 = fp32 C, 1 = fp16 C, 2 = fp32 C plus fp16 copy to C2.
template <int ACTIN, int ACTOUT, int BIAS, int MT, int OUTH>
__global__ __launch_bounds__(256, 3)
void gemm_mma(const float* __restrict__ A, int wtile0,
              const float* __restrict__ bias, void* __restrict__ Cv,
              __half* __restrict__ C2) {
    extern __shared__ char smem[];
    const uint32_t sb = smem_u32(smem);
    const int tid = threadIdx.x, lane = tid & 31, wid = tid >> 5;
    const int warp_m = (wid & 1) * 32;
    const int warp_n = (wid >> 1) * 32;
    const int n0 = blockIdx.x * 64;

    const int a_row = lane & 15;
    const int a_kh = (lane >> 4) & 1;
    const int b_row = (lane & 7) | (((lane >> 4) & 1) << 3);
    const int b_kh = (lane >> 3) & 1;

    // ---- fill + split A tile (64 rows x 128 k), once per CTA ----
    for (int i = tid; i < 2048; i += 256) {
        int r = i >> 5, k = (i & 31) << 2;
        int gr = n0 + r;
        if (gr >= NN) gr = NN - 1;  // clamp; padded rows discarded at store
        float4 v = *(const float4*)(A + (size_t)gr * 128 + k);
        if (ACTIN) {
            v.x = fmaxf(v.x, 0.f); v.y = fmaxf(v.y, 0.f);
            v.z = fmaxf(v.z, 0.f); v.w = fmaxf(v.w, 0.f);
        }
        uint2 hi, lo;
        split4h(v, hi, lo);
        uint32_t o = swz((uint32_t)r, (uint32_t)(k * 2));
        *(uint2*)(smem + SM_A_HI + o) = hi;
        *(uint2*)(smem + SM_A_LO + o) = lo;
    }

    for (int mt = 0; mt < MT; mt++) {
        // ---- W fill: identity cp.async copy of the pre-swizzled fp16 blob ----
        const char* wb = (const char*)g_wh + (size_t)(wtile0 + mt) * 32768;
        for (int i = tid; i < 2048; i += 256) {
            cpa16(sb + SM_B + i * 16, wb + i * 16);
        }
        CP_COMMIT_WAIT();
        __syncthreads();

        float acc[2][4][4];
#pragma unroll
        for (int t = 0; t < 2; t++)
#pragma unroll
            for (int u = 0; u < 4; u++)
#pragma unroll
                for (int q = 0; q < 4; q++) acc[t][u][q] = 0.f;

#pragma unroll 1
        for (int p = 0; p < 2; p++) {  // A_hi @ B, A_lo @ B
            const uint32_t Ab = sb + (p ? SM_A_LO : SM_A_HI);
#pragma unroll
            for (int ks = 0; ks < 8; ks++) {
                const uint32_t c2a = ks * 32 + a_kh * 16;
                const uint32_t c2b = ks * 32 + b_kh * 16;
                uint32_t afr[2][4], bfr[4][2];
#pragma unroll
                for (int t = 0; t < 2; t++)
                    ldsm4(afr[t], Ab + swz(warp_m + t * 16 + a_row, c2a));
#pragma unroll
                for (int ub = 0; ub < 2; ub++) {
                    uint32_t tmp[4];
                    ldsm4(tmp, sb + SM_B + swz(warp_n + ub * 16 + b_row, c2b));
                    bfr[2 * ub][0] = tmp[0]; bfr[2 * ub][1] = tmp[1];
                    bfr[2 * ub + 1][0] = tmp[2]; bfr[2 * ub + 1][1] = tmp[3];
                }
#pragma unroll
                for (int t = 0; t < 2; t++)
#pragma unroll
                    for (int u = 0; u < 4; u++)
                        mma16816(acc[t][u], afr[t], bfr[u]);
            }
        }

        // ---- epilogue ----
        const int M = MT * 128;
        const int row0 = n0 + warp_m + (lane >> 2);
        const int colb = mt * 128 + warp_n + (lane & 3) * 2;
#pragma unroll
        for (int u = 0; u < 4; u++) {
            const int c = colb + u * 8;
            float b0 = 0.f, b1 = 0.f;
            if (BIAS) { b0 = __ldg(bias + c); b1 = __ldg(bias + c + 1); }
#pragma unroll
            for (int t = 0; t < 2; t++) {
                const int r = row0 + t * 16;
                float v0 = acc[t][u][0] + b0, v1 = acc[t][u][1] + b1;
                float v2 = acc[t][u][2] + b0, v3 = acc[t][u][3] + b1;
                if (ACTOUT) {
                    v0 = fmaxf(v0, 0.f); v1 = fmaxf(v1, 0.f);
                    v2 = fmaxf(v2, 0.f); v3 = fmaxf(v3, 0.f);
                }
                if (OUTH == 1) {
                    __half2* C = (__half2*)Cv;
                    if (r < NN) C[((size_t)r * M + c) >> 1] = __floats2half2_rn(v0, v1);
                    if (r + 8 < NN) C[((size_t)(r + 8) * M + c) >> 1] = __floats2half2_rn(v2, v3);
                } else {
                    float* C = (float*)Cv;
                    if (r < NN) {
                        *(float2*)(C + (size_t)r * M + c) = make_float2(v0, v1);
                        if (OUTH == 2)
                            *(__half2*)(C2 + (size_t)r * M + c) = __floats2half2_rn(v0, v1);
                    }
                    if (r + 8 < NN) {
                        *(float2*)(C + (size_t)(r + 8) * M + c) = make_float2(v2, v3);
                        if (OUTH == 2)
                            *(__half2*)(C2 + (size_t)(r + 8) * M + c) = __floats2half2_rn(v2, v3);
                    }
                }
            }
        }
        if (MT > 1) __syncthreads();  // B consumed before next mt overwrites
    }
}

// ---------------- zero agg ----------------
__global__ void zero_kernel(float4* __restrict__ p) {
    int i = blockIdx.x * blockDim.x + threadIdx.x;
    p[i] = make_float4(0.f, 0.f, 0.f, 0.f);
}

// ---------------- scatter-add: agg[dst] += h16[src], warp per edge (fp16 gather) ----------------
__global__ void scatter_kernel(const __half2* __restrict__ h16,
                               const void* __restrict__ ei_raw,
                               float* __restrict__ agg) {
    int t = blockIdx.x * blockDim.x + threadIdx.x;
    int e = t >> 5;
    int lane = t & 31;
    if (e >= EE) return;

    const long long* e64 = (const long long*)ei_raw;
    bool is64 = (((unsigned long long)e64[0] < (unsigned long long)NN) &&
                 ((unsigned long long)e64[1] < (unsigned long long)NN));
    int src, dst;
    if (is64) {
        src = (int)e64[e];
        dst = (int)e64[EE + e];
    } else {
        const int* e32 = (const int*)ei_raw;
        src = e32[e];
        dst = e32[EE + e];
    }
    // gather 8B (4 halves) per lane -> 256B per edge row
    const __half2* sp = h16 + (size_t)src * 64 + lane * 2;
    float2 a = __half22float2(sp[0]);
    float2 b = __half22float2(sp[1]);
    float* p = agg + (size_t)dst * DD + lane * 4;
    asm volatile("red.global.add.v4.f32 [%0], {%1, %2, %3, %4};"
                 :: "l"(p), "f"(a.x), "f"(a.y), "f"(b.x), "f"(b.y)
                 : "memory");
}

// ---------------- GRU gate fusion (fp16 gi/gh inputs; writes h fp32 + h16 fp16) ----------------
static __device__ __forceinline__ float gate1(float ir, float iz, float in_,
                                              float hr, float hz, float hn, float hv) {
    float r = sigf(ir + hr);
    float z = sigf(iz + hz);
    float n = tanhf(in_ + r * hn);
    return (1.f - z) * n + z * hv;
}

__global__ void gru_gate(const __half2* __restrict__ gi, const __half2* __restrict__ gh,
                         float* __restrict__ h, __half2* __restrict__ h16) {
    int t = blockIdx.x * blockDim.x + threadIdx.x;  // NN*32 threads, 4 dims each
    int n = t >> 5;
    int d4 = (t & 31) << 2;
    if (n >= NN) return;
    size_t bi = ((size_t)n * 384 + d4) >> 1;  // half2 index
    float2 ir01 = __half22float2(gi[bi]),       ir23 = __half22float2(gi[bi + 1]);
    float2 iz01 = __half22float2(gi[bi + 64]),  iz23 = __half22float2(gi[bi + 65]);
    float2 in01 = __half22float2(gi[bi + 128]), in23 = __half22float2(gi[bi + 129]);
    float2 hr01 = __half22float2(gh[bi]),       hr23 = __half22float2(gh[bi + 1]);
    float2 hz01 = __half22float2(gh[bi + 64]),  hz23 = __half22float2(gh[bi + 65]);
    float2 hn01 = __half22float2(gh[bi + 128]), hn23 = __half22float2(gh[bi + 129]);
    float4* hp = (float4*)(h + (size_t)n * 128 + d4);
    float4 hv = *hp;
    float4 o;
    o.x = gate1(ir01.x, iz01.x, in01.x, hr01.x, hz01.x, hn01.x, hv.x);
    o.y = gate1(ir01.y, iz01.y, in01.y, hr01.y, hz01.y, hn01.y, hv.y);
    o.z = gate1(ir23.x, iz23.x, in23.x, hr23.x, hz23.x, hn23.x, hv.z);
    o.w = gate1(ir23.y, iz23.y, in23.y, hr23.y, hz23.y, hn23.y, hv.w);
    *hp = o;
    size_t hi2 = ((size_t)n * 128 + d4) >> 1;
    h16[hi2] = __floats2half2_rn(o.x, o.y);
    h16[hi2 + 1] = __floats2half2_rn(o.z, o.w);
}

// ---------------- launcher ----------------
extern "C" void kernel_launch(void* const* d_in, const int* in_sizes, int n_in,
                              void* d_out, int out_size) {
    const float* x     = (const float*)d_in[0];
    const void*  ei    = (const void*)d_in[1];
    const float* W1    = (const float*)d_in[2];
    const float* b1    = (const float*)d_in[3];
    const float* Wconv = (const float*)d_in[4];
    const float* Wih   = (const float*)d_in[5];
    const float* Whh   = (const float*)d_in[6];
    const float* bih   = (const float*)d_in[7];
    const float* bhh   = (const float*)d_in[8];
    const float* W2    = (const float*)d_in[9];
    const float* b2    = (const float*)d_in[10];
    float* out = (float*)d_out;

    float *h, *agg;
    __half *h16, *gi, *gh;
    cudaGetSymbolAddress((void**)&h, g_h);
    cudaGetSymbolAddress((void**)&h16, g_h16);
    cudaGetSymbolAddress((void**)&agg, g_agg);
    cudaGetSymbolAddress((void**)&gi, g_gi);
    cudaGetSymbolAddress((void**)&gh, g_gh);

    cudaFuncSetAttribute(gemm_mma<0, 1, 1, 1, 2>, cudaFuncAttributeMaxDynamicSharedMemorySize, SM_TOTAL);
    cudaFuncSetAttribute(gemm_mma<0, 0, 1, 3, 1>, cudaFuncAttributeMaxDynamicSharedMemorySize, SM_TOTAL);
    cudaFuncSetAttribute(gemm_mma<1, 0, 1, 3, 0>, cudaFuncAttributeMaxDynamicSharedMemorySize, SM_TOTAL);

    // high-priority side stream + fork/join events (per-call; capture-safe).
    // Fall back to a plain stream if the priority path misbehaves.
    cudaStream_t s2 = 0;
    int prLo = 0, prHi = 0;
    if (cudaDeviceGetStreamPriorityRange(&prLo, &prHi) != cudaSuccess ||
        cudaStreamCreateWithPriority(&s2, cudaStreamNonBlocking, prHi) != cudaSuccess) {
        cudaGetLastError();  // clear sticky error
        cudaStreamCreateWithFlags(&s2, cudaStreamNonBlocking);
    }
    cudaEvent_t evH[3], evG[3];
    for (int i = 0; i < 3; i++) {
        cudaEventCreateWithFlags(&evH[i], cudaEventDisableTiming);
        cudaEventCreateWithFlags(&evG[i], cudaEventDisableTiming);
    }

    // prepasses: Wfused then convert+swizzle all 16 tiles to fp16
    wfused_kernel<<<(3 * 384 * 128 + 255) / 256, 256>>>(Wih, Wconv);
    convert_w<<<(2048 * 128 + 255) / 256, 256>>>(W1, Whh, W2);
    // prologue zero of agg overlaps the prepasses' tail
    zero_kernel<<<NN * DD / 4 / 256, 256>>>((float4*)agg);

    // h = relu(x @ W1^T + b1), fp32 + fp16 copies
    gemm_mma<0, 1, 1, 1, 2><<<NT64, 256, SM_TOTAL>>>(x, 0, b1, h, h16);

    for (int l = 0; l < 3; l++) {
        // fork: gh = h @ Whh^T + bhh on high-priority s2, overlapping scatter on main
        cudaEventRecord(evH[l], 0);
        cudaStreamWaitEvent(s2, evH[l], 0);
        gemm_mma<0, 0, 1, 3, 1><<<NT64, 256, SM_TOTAL, s2>>>(h, 1, bhh, gh, nullptr);
        cudaEventRecord(evG[l], s2);

        // main: agg = scatter(h16); gi = agg @ Wfused[l]^T + bih
        scatter_kernel<<<(EE * 32) / 256, 256>>>((const __half2*)h16, ei, agg);
        gemm_mma<0, 0, 1, 3, 1><<<NT64, 256, SM_TOTAL>>>(agg, 7 + 3 * l, bih, gi, nullptr);
        // re-zero agg for the next layer; overlaps gru (gi has consumed agg)
        if (l < 2) zero_kernel<<<NN * DD / 4 / 256, 256>>>((float4*)agg);

        // join, then h = GRU(gi, gh) -> h fp32 + h16
        cudaStreamWaitEvent(0, evG[l], 0);
        gru_gate<<<NN * 32 / 256, 256>>>((const __half2*)gi, (const __half2*)gh, h, (__half2*)h16);
    }

    // out = relu(h) @ W2^T + b2
    gemm_mma<1, 0, 1, 3, 0><<<NT64, 256, SM_TOTAL>>>(h, 4, b2, out, nullptr);

    for (int i = 0; i < 3; i++) {
        cudaEventDestroy(evH[i]);
        cudaEventDestroy(evG[i]);
    }
    cudaStreamDestroy(s2);
}

// round 16
// speedup vs baseline: 1.1742x; 1.1742x over previous
#include <cuda_runtime.h>
#include <cuda_fp16.h>
#include <cstdint>

#define NN 100000
#define DD 128
#define EE 600000
#define NT64 1563  // ceil(NN/64)
#define NB_SCAN 391  // ceil(NN/256)

// ---------------- scratch (device globals: no runtime allocation) ----------------
__device__ float g_h[(size_t)NN * DD];
__device__ __half g_h16[(size_t)NN * DD];      // fp16 copy of h (L2-resident gather source)
__device__ float g_agg[(size_t)NN * DD];
__device__ __half g_gi[(size_t)NN * 3 * DD];   // fp16 gate pre-activations
__device__ __half g_gh[(size_t)NN * 3 * DD];
__device__ float g_wf[3 * 384 * 128];          // Wfused[l] = Wih @ Wconv[l]
__device__ __half g_wh[16 * 16384];            // pre-swizzled fp16 weight tiles
// CSR structures (rebuilt every launch)
__device__ int g_deg[NN];
__device__ int g_off[NN];
__device__ int g_pos[NN];
__device__ int g_csr[EE];
__device__ int g_bsum[512];
__device__ int g_bsum2[512];

// ---------------- helpers ----------------
static __device__ __forceinline__ uint32_t smem_u32(const void* p) {
    uint32_t a;
    asm("{ .reg .u64 t; cvta.to.shared.u64 t, %1; cvt.u32.u64 %0, t; }" : "=r"(a) : "l"(p));
    return a;
}
static __device__ __forceinline__ void ldsm4(uint32_t* r, uint32_t addr) {
    asm volatile("ldmatrix.sync.aligned.m8n8.x4.shared.b16 {%0,%1,%2,%3}, [%4];"
                 : "=r"(r[0]), "=r"(r[1]), "=r"(r[2]), "=r"(r[3]) : "r"(addr));
}
static __device__ __forceinline__ void mma16816(float* d, const uint32_t* a, const uint32_t* b) {
    asm volatile(
        "mma.sync.aligned.m16n8k16.row.col.f32.f16.f16.f32 "
        "{%0,%1,%2,%3}, {%4,%5,%6,%7}, {%8,%9}, {%0,%1,%2,%3};"
        : "+f"(d[0]), "+f"(d[1]), "+f"(d[2]), "+f"(d[3])
        : "r"(a[0]), "r"(a[1]), "r"(a[2]), "r"(a[3]), "r"(b[0]), "r"(b[1]));
}
static __device__ __forceinline__ void cpa16(uint32_t dst, const void* src) {
    asm volatile("cp.async.cg.shared.global [%0], [%1], 16;" :: "r"(dst), "l"(src) : "memory");
}
#define CP_COMMIT_WAIT() \
    asm volatile("cp.async.commit_group;\ncp.async.wait_group 0;" ::: "memory")

static __device__ __forceinline__ uint32_t swz(uint32_t r, uint32_t c2) {
    return r * 256 + (c2 ^ ((r & 7) << 4));
}

// Dekker split of 4 floats into fp16 hi/lo packed words (~22-bit effective mantissa)
static __device__ __forceinline__ void split4h(float4 v, uint2& hi, uint2& lo) {
    __half h0 = __float2half(v.x), h1 = __float2half(v.y);
    __half h2 = __float2half(v.z), h3 = __float2half(v.w);
    __half l0 = __float2half(v.x - __half2float(h0));
    __half l1 = __float2half(v.y - __half2float(h1));
    __half l2 = __float2half(v.z - __half2float(h2));
    __half l3 = __float2half(v.w - __half2float(h3));
    hi.x = (uint32_t)__half_as_ushort(h0) | ((uint32_t)__half_as_ushort(h1) << 16);
    hi.y = (uint32_t)__half_as_ushort(h2) | ((uint32_t)__half_as_ushort(h3) << 16);
    lo.x = (uint32_t)__half_as_ushort(l0) | ((uint32_t)__half_as_ushort(l1) << 16);
    lo.y = (uint32_t)__half_as_ushort(l2) | ((uint32_t)__half_as_ushort(l3) << 16);
}

static __device__ __forceinline__ float sigf(float x) { return 1.f / (1.f + __expf(-x)); }

// edge-index dtype probe (int64 vs int32), shared by CSR kernels
static __device__ __forceinline__ void edge_pair(const void* ei_raw, int e, int& src, int& dst) {
    const long long* e64 = (const long long*)ei_raw;
    bool is64 = (((unsigned long long)e64[0] < (unsigned long long)NN) &&
                 ((unsigned long long)e64[1] < (unsigned long long)NN));
    if (is64) {
        src = (int)e64[e];
        dst = (int)e64[EE + e];
    } else {
        const int* e32 = (const int*)ei_raw;
        src = e32[e];
        dst = e32[EE + e];
    }
}

// ---------------- prepass: Wfused + weight conversion ----------------
__global__ void wfused_kernel(const float* __restrict__ Wih, const float* __restrict__ Wconv) {
    int i = blockIdx.x * blockDim.x + threadIdx.x;
    if (i >= 3 * 384 * 128) return;
    int l = i / (384 * 128), r = (i >> 7) % 384, k = i & 127;
    const float* wc = Wconv + (size_t)l * 128 * 128;
    float s = 0.f;
#pragma unroll 8
    for (int j = 0; j < 128; j++) s = fmaf(__ldg(Wih + r * 128 + j), __ldg(wc + j * 128 + k), s);
    g_wf[i] = s;
}

// rows: [0,128) W1; [128,512) Whh; [512,896) W2; [896,2048) Wfused
__global__ void convert_w(const float* __restrict__ W1, const float* __restrict__ Whh,
                          const float* __restrict__ W2) {
    int i = blockIdx.x * blockDim.x + threadIdx.x;
    if (i >= 2048 * 128) return;
    int row = i >> 7, k = i & 127;
    float v;
    if (row < 128)       v = W1[(size_t)row * 128 + k];
    else if (row < 512)  v = Whh[(size_t)(row - 128) * 128 + k];
    else if (row < 896)  v = W2[(size_t)(row - 512) * 128 + k];
    else                 v = g_wf[(size_t)(row - 896) * 128 + k];
    int tile = row >> 7, tr = row & 127;
    uint32_t o = swz((uint32_t)tr, (uint32_t)(2 * k));
    *(__half*)((char*)g_wh + (size_t)tile * 32768 + o) = __float2half(v);
}

// ---------------- CSR build (once per launch) ----------------
__global__ void zero_deg() {
    int i = blockIdx.x * blockDim.x + threadIdx.x;
    if (i < NN) g_deg[i] = 0;
}
__global__ void count_kernel(const void* __restrict__ ei_raw) {
    int e = blockIdx.x * blockDim.x + threadIdx.x;
    if (e >= EE) return;
    int src, dst;
    edge_pair(ei_raw, e, src, dst);
    atomicAdd(&g_deg[dst], 1);
}
__global__ void scan1() {  // per-block exclusive scan of g_deg -> g_off, block totals -> g_bsum
    __shared__ int s[256];
    int i = blockIdx.x * 256 + threadIdx.x;
    int tid = threadIdx.x;
    int v = (i < NN) ? g_deg[i] : 0;
    s[tid] = v;
    __syncthreads();
    for (int d = 1; d < 256; d <<= 1) {
        int t = (tid >= d) ? s[tid - d] : 0;
        __syncthreads();
        s[tid] += t;
        __syncthreads();
    }
    if (i < NN) g_off[i] = s[tid] - v;
    if (tid == 255) g_bsum[blockIdx.x] = s[255];
}
__global__ void scan2() {  // single block: exclusive scan of block sums
    __shared__ int s[512];
    int tid = threadIdx.x;
    int v = (tid < NB_SCAN) ? g_bsum[tid] : 0;
    s[tid] = v;
    __syncthreads();
    for (int d = 1; d < 512; d <<= 1) {
        int t = (tid >= d) ? s[tid - d] : 0;
        __syncthreads();
        s[tid] += t;
        __syncthreads();
    }
    if (tid < NB_SCAN) g_bsum2[tid] = s[tid] - v;
}
__global__ void scan3() {  // add block offsets; init fill cursors
    int i = blockIdx.x * 256 + threadIdx.x;
    if (i >= NN) return;
    int o = g_off[i] + g_bsum2[blockIdx.x];
    g_off[i] = o;
    g_pos[i] = o;
}
__global__ void fill_kernel(const void* __restrict__ ei_raw) {
    int e = blockIdx.x * blockDim.x + threadIdx.x;
    if (e >= EE) return;
    int src, dst;
    edge_pair(ei_raw, e, src, dst);
    int p = atomicAdd(&g_pos[dst], 1);
    g_csr[p] = src;
}

// ---------------- per-layer aggregation: warp-per-node CSR gather ----------------
__global__ void gather_agg(const __half2* __restrict__ h16, float* __restrict__ agg) {
    int t = blockIdx.x * blockDim.x + threadIdx.x;
    int n = t >> 5;
    int lane = t & 31;
    if (n >= NN) return;
    int e0 = g_off[n];
    int e1 = (n + 1 < NN) ? g_off[n + 1] : EE;
    float4 acc = make_float4(0.f, 0.f, 0.f, 0.f);
    int e = e0;
    for (; e + 1 < e1; e += 2) {  // unroll-2 for MLP
        int s0 = g_csr[e], s1 = g_csr[e + 1];
        const __half2* p0 = h16 + (size_t)s0 * 64 + lane * 2;
        const __half2* p1 = h16 + (size_t)s1 * 64 + lane * 2;
        float2 a0 = __half22float2(p0[0]), b0 = __half22float2(p0[1]);
        float2 a1 = __half22float2(p1[0]), b1 = __half22float2(p1[1]);
        acc.x += a0.x + a1.x;
        acc.y += a0.y + a1.y;
        acc.z += b0.x + b1.x;
        acc.w += b0.y + b1.y;
    }
    if (e < e1) {
        int s0 = g_csr[e];
        const __half2* p0 = h16 + (size_t)s0 * 64 + lane * 2;
        float2 a0 = __half22float2(p0[0]), b0 = __half22float2(p0[1]);
        acc.x += a0.x; acc.y += a0.y; acc.z += b0.x; acc.w += b0.y;
    }
    *(float4*)(agg + (size_t)n * DD + lane * 4) = acc;
}

// SMEM: A hi/lo (64x128 = 16KB each), B (128x128 = 32KB) = 64KB -> occ 3
#define SM_A_HI 0
#define SM_A_LO 16384
#define SM_B 32768
#define SM_TOTAL 65536

// ======== mma.sync GEMM: C[N, MT*128] = act( A[N,128] @ W^T + b ) ========
// Tile 64(M) x 128(N); 8 warps; 2-pass fp16 split (A hi/lo x B fp16).
// OUTH: 0 = fp32 C, 1 = fp16 C, 2 = fp32 C plus fp16 copy to C2.
template <int ACTIN, int ACTOUT, int BIAS, int MT, int OUTH>
__global__ __launch_bounds__(256, 3)
void gemm_mma(const float* __restrict__ A, int wtile0,
              const float* __restrict__ bias, void* __restrict__ Cv,
              __half* __restrict__ C2) {
    extern __shared__ char smem[];
    const uint32_t sb = smem_u32(smem);
    const int tid = threadIdx.x, lane = tid & 31, wid = tid >> 5;
    const int warp_m = (wid & 1) * 32;
    const int warp_n = (wid >> 1) * 32;
    const int n0 = blockIdx.x * 64;

    const int a_row = lane & 15;
    const int a_kh = (lane >> 4) & 1;
    const int b_row = (lane & 7) | (((lane >> 4) & 1) << 3);
    const int b_kh = (lane >> 3) & 1;

    // ---- fill + split A tile (64 rows x 128 k), once per CTA ----
    for (int i = tid; i < 2048; i += 256) {
        int r = i >> 5, k = (i & 31) << 2;
        int gr = n0 + r;
        if (gr >= NN) gr = NN - 1;  // clamp; padded rows discarded at store
        float4 v = *(const float4*)(A + (size_t)gr * 128 + k);
        if (ACTIN) {
            v.x = fmaxf(v.x, 0.f); v.y = fmaxf(v.y, 0.f);
            v.z = fmaxf(v.z, 0.f); v.w = fmaxf(v.w, 0.f);
        }
        uint2 hi, lo;
        split4h(v, hi, lo);
        uint32_t o = swz((uint32_t)r, (uint32_t)(k * 2));
        *(uint2*)(smem + SM_A_HI + o) = hi;
        *(uint2*)(smem + SM_A_LO + o) = lo;
    }

    for (int mt = 0; mt < MT; mt++) {
        // ---- W fill: identity cp.async copy of the pre-swizzled fp16 blob ----
        const char* wb = (const char*)g_wh + (size_t)(wtile0 + mt) * 32768;
        for (int i = tid; i < 2048; i += 256) {
            cpa16(sb + SM_B + i * 16, wb + i * 16);
        }
        CP_COMMIT_WAIT();
        __syncthreads();

        float acc[2][4][4];
#pragma unroll
        for (int t = 0; t < 2; t++)
#pragma unroll
            for (int u = 0; u < 4; u++)
#pragma unroll
                for (int q = 0; q < 4; q++) acc[t][u][q] = 0.f;

#pragma unroll 1
        for (int p = 0; p < 2; p++) {  // A_hi @ B, A_lo @ B
            const uint32_t Ab = sb + (p ? SM_A_LO : SM_A_HI);
#pragma unroll
            for (int ks = 0; ks < 8; ks++) {
                const uint32_t c2a = ks * 32 + a_kh * 16;
                const uint32_t c2b = ks * 32 + b_kh * 16;
                uint32_t afr[2][4], bfr[4][2];
#pragma unroll
                for (int t = 0; t < 2; t++)
                    ldsm4(afr[t], Ab + swz(warp_m + t * 16 + a_row, c2a));
#pragma unroll
                for (int ub = 0; ub < 2; ub++) {
                    uint32_t tmp[4];
                    ldsm4(tmp, sb + SM_B + swz(warp_n + ub * 16 + b_row, c2b));
                    bfr[2 * ub][0] = tmp[0]; bfr[2 * ub][1] = tmp[1];
                    bfr[2 * ub + 1][0] = tmp[2]; bfr[2 * ub + 1][1] = tmp[3];
                }
#pragma unroll
                for (int t = 0; t < 2; t++)
#pragma unroll
                    for (int u = 0; u < 4; u++)
                        mma16816(acc[t][u], afr[t], bfr[u]);
            }
        }

        // ---- epilogue ----
        const int M = MT * 128;
        const int row0 = n0 + warp_m + (lane >> 2);
        const int colb = mt * 128 + warp_n + (lane & 3) * 2;
#pragma unroll
        for (int u = 0; u < 4; u++) {
            const int c = colb + u * 8;
            float b0 = 0.f, b1 = 0.f;
            if (BIAS) { b0 = __ldg(bias + c); b1 = __ldg(bias + c + 1); }
#pragma unroll
            for (int t = 0; t < 2; t++) {
                const int r = row0 + t * 16;
                float v0 = acc[t][u][0] + b0, v1 = acc[t][u][1] + b1;
                float v2 = acc[t][u][2] + b0, v3 = acc[t][u][3] + b1;
                if (ACTOUT) {
                    v0 = fmaxf(v0, 0.f); v1 = fmaxf(v1, 0.f);
                    v2 = fmaxf(v2, 0.f); v3 = fmaxf(v3, 0.f);
                }
                if (OUTH == 1) {
                    __half2* C = (__half2*)Cv;
                    if (r < NN) C[((size_t)r * M + c) >> 1] = __floats2half2_rn(v0, v1);
                    if (r + 8 < NN) C[((size_t)(r + 8) * M + c) >> 1] = __floats2half2_rn(v2, v3);
                } else {
                    float* C = (float*)Cv;
                    if (r < NN) {
                        *(float2*)(C + (size_t)r * M + c) = make_float2(v0, v1);
                        if (OUTH == 2)
                            *(__half2*)(C2 + (size_t)r * M + c) = __floats2half2_rn(v0, v1);
                    }
                    if (r + 8 < NN) {
                        *(float2*)(C + (size_t)(r + 8) * M + c) = make_float2(v2, v3);
                        if (OUTH == 2)
                            *(__half2*)(C2 + (size_t)(r + 8) * M + c) = __floats2half2_rn(v2, v3);
                    }
                }
            }
        }
        if (MT > 1) __syncthreads();  // B consumed before next mt overwrites
    }
}

// ---------------- GRU gate fusion (fp16 gi/gh; writes h fp32 + h16 fp16) ----------------
static __device__ __forceinline__ float gate1(float ir, float iz, float in_,
                                              float hr, float hz, float hn, float hv) {
    float r = sigf(ir + hr);
    float z = sigf(iz + hz);
    float n = tanhf(in_ + r * hn);
    return (1.f - z) * n + z * hv;
}

__global__ void gru_gate(const __half2* __restrict__ gi, const __half2* __restrict__ gh,
                         float* __restrict__ h, __half2* __restrict__ h16) {
    int t = blockIdx.x * blockDim.x + threadIdx.x;
    int n = t >> 5;
    int d4 = (t & 31) << 2;
    if (n >= NN) return;
    size_t bi = ((size_t)n * 384 + d4) >> 1;
    float2 ir01 = __half22float2(gi[bi]),       ir23 = __half22float2(gi[bi + 1]);
    float2 iz01 = __half22float2(gi[bi + 64]),  iz23 = __half22float2(gi[bi + 65]);
    float2 in01 = __half22float2(gi[bi + 128]), in23 = __half22float2(gi[bi + 129]);
    float2 hr01 = __half22float2(gh[bi]),       hr23 = __half22float2(gh[bi + 1]);
    float2 hz01 = __half22float2(gh[bi + 64]),  hz23 = __half22float2(gh[bi + 65]);
    float2 hn01 = __half22float2(gh[bi + 128]), hn23 = __half22float2(gh[bi + 129]);
    float4* hp = (float4*)(h + (size_t)n * 128 + d4);
    float4 hv = *hp;
    float4 o;
    o.x = gate1(ir01.x, iz01.x, in01.x, hr01.x, hz01.x, hn01.x, hv.x);
    o.y = gate1(ir01.y, iz01.y, in01.y, hr01.y, hz01.y, hn01.y, hv.y);
    o.z = gate1(ir23.x, iz23.x, in23.x, hr23.x, hz23.x, hn23.x, hv.z);
    o.w = gate1(ir23.y, iz23.y, in23.y, hr23.y, hz23.y, hn23.y, hv.w);
    *hp = o;
    size_t hi2 = ((size_t)n * 128 + d4) >> 1;
    h16[hi2] = __floats2half2_rn(o.x, o.y);
    h16[hi2 + 1] = __floats2half2_rn(o.z, o.w);
}

// ---------------- launcher ----------------
extern "C" void kernel_launch(void* const* d_in, const int* in_sizes, int n_in,
                              void* d_out, int out_size) {
    const float* x     = (const float*)d_in[0];
    const void*  ei    = (const void*)d_in[1];
    const float* W1    = (const float*)d_in[2];
    const float* b1    = (const float*)d_in[3];
    const float* Wconv = (const float*)d_in[4];
    const float* Wih   = (const float*)d_in[5];
    const float* Whh   = (const float*)d_in[6];
    const float* bih   = (const float*)d_in[7];
    const float* bhh   = (const float*)d_in[8];
    const float* W2    = (const float*)d_in[9];
    const float* b2    = (const float*)d_in[10];
    float* out = (float*)d_out;

    float *h, *agg;
    __half *h16, *gi, *gh;
    cudaGetSymbolAddress((void**)&h, g_h);
    cudaGetSymbolAddress((void**)&h16, g_h16);
    cudaGetSymbolAddress((void**)&agg, g_agg);
    cudaGetSymbolAddress((void**)&gi, g_gi);
    cudaGetSymbolAddress((void**)&gh, g_gh);

    cudaFuncSetAttribute(gemm_mma<0, 1, 1, 1, 2>, cudaFuncAttributeMaxDynamicSharedMemorySize, SM_TOTAL);
    cudaFuncSetAttribute(gemm_mma<0, 0, 1, 3, 1>, cudaFuncAttributeMaxDynamicSharedMemorySize, SM_TOTAL);
    cudaFuncSetAttribute(gemm_mma<1, 0, 1, 3, 0>, cudaFuncAttributeMaxDynamicSharedMemorySize, SM_TOTAL);

    // plain non-blocking side stream + fork/join events
    cudaStream_t s2;
    cudaStreamCreateWithFlags(&s2, cudaStreamNonBlocking);
    cudaEvent_t evFork, evCSR, evH[3], evG[3];
    cudaEventCreateWithFlags(&evFork, cudaEventDisableTiming);
    cudaEventCreateWithFlags(&evCSR, cudaEventDisableTiming);
    for (int i = 0; i < 3; i++) {
        cudaEventCreateWithFlags(&evH[i], cudaEventDisableTiming);
        cudaEventCreateWithFlags(&evG[i], cudaEventDisableTiming);
    }

    // capture-legal fork: s2 must join the capture graph via an event recorded
    // on the capture-origin stream BEFORE any launch on s2.
    cudaEventRecord(evFork, 0);
    cudaStreamWaitEvent(s2, evFork, 0);

    // prepass: CSR build on s2 (overlaps weight prep + linear1 on main)
    zero_deg<<<NB_SCAN, 256, 0, s2>>>();
    count_kernel<<<(EE + 255) / 256, 256, 0, s2>>>(ei);
    scan1<<<NB_SCAN, 256, 0, s2>>>();
    scan2<<<1, 512, 0, s2>>>();
    scan3<<<NB_SCAN, 256, 0, s2>>>();
    fill_kernel<<<(EE + 255) / 256, 256, 0, s2>>>(ei);
    cudaEventRecord(evCSR, s2);

    // prepasses: weights (main stream)
    wfused_kernel<<<(3 * 384 * 128 + 255) / 256, 256>>>(Wih, Wconv);
    convert_w<<<(2048 * 128 + 255) / 256, 256>>>(W1, Whh, W2);

    // h = relu(x @ W1^T + b1), fp32 + fp16 copies
    gemm_mma<0, 1, 1, 1, 2><<<NT64, 256, SM_TOTAL>>>(x, 0, b1, h, h16);

    cudaStreamWaitEvent(0, evCSR, 0);  // CSR ready before first gather

    for (int l = 0; l < 3; l++) {
        // fork: gh = h @ Whh^T + bhh on s2, may overlap gather on main
        cudaEventRecord(evH[l], 0);
        cudaStreamWaitEvent(s2, evH[l], 0);
        gemm_mma<0, 0, 1, 3, 1><<<NT64, 256, SM_TOTAL, s2>>>(h, 1, bhh, gh, nullptr);
        cudaEventRecord(evG[l], s2);

        // main: agg = CSR-gather(h16); gi = agg @ Wfused[l]^T + bih
        gather_agg<<<(NN * 32 + 255) / 256, 256>>>((const __half2*)h16, agg);
        gemm_mma<0, 0, 1, 3, 1><<<NT64, 256, SM_TOTAL>>>(agg, 7 + 3 * l, bih, gi, nullptr);

        // join, then h = GRU(gi, gh) -> h fp32 + h16
        cudaStreamWaitEvent(0, evG[l], 0);
        gru_gate<<<NN * 32 / 256, 256>>>((const __half2*)gi, (const __half2*)gh, h, (__half2*)h16);
    }

    // out = relu(h) @ W2^T + b2
    gemm_mma<1, 0, 1, 3, 0><<<NT64, 256, SM_TOTAL>>>(h, 4, b2, out, nullptr);

    cudaEventDestroy(evFork);
    cudaEventDestroy(evCSR);
    for (int i = 0; i < 3; i++) {
        cudaEventDestroy(evH[i]);
        cudaEventDestroy(evG[i]);
    }
    cudaStreamDestroy(s2);
}

// round 17
// speedup vs baseline: 1.2627x; 1.0753x over previous
#include <cuda_runtime.h>
#include <cuda_fp16.h>
#include <cstdint>

#define NN 100000
#define DD 128
#define EE 600000
#define NT64 1563  // ceil(NN/64)
#define NB_SCAN 391  // ceil(NN/256)

// ---------------- scratch (device globals: no runtime allocation) ----------------
__device__ float g_h[(size_t)NN * DD];
__device__ __half g_h16[(size_t)NN * DD];      // fp16 copy of h (gather + gh-GEMM source)
__device__ float g_agg[(size_t)NN * DD];
__device__ __half g_gi[(size_t)NN * 3 * DD];   // fp16 gate pre-activations
__device__ __half g_gh[(size_t)NN * 3 * DD];
__device__ float g_wf[3 * 384 * 128];          // Wfused[l] = Wih @ Wconv[l]
__device__ __half g_wh[16 * 16384];            // pre-swizzled fp16 weight tiles
// CSR structures (rebuilt every launch)
__device__ int g_deg[NN];
__device__ int g_off[NN];
__device__ int g_pos[NN];
__device__ int g_csr[EE];
__device__ int g_bsum[512];
__device__ int g_bsum2[512];

// ---------------- helpers ----------------
static __device__ __forceinline__ uint32_t smem_u32(const void* p) {
    uint32_t a;
    asm("{ .reg .u64 t; cvta.to.shared.u64 t, %1; cvt.u32.u64 %0, t; }" : "=r"(a) : "l"(p));
    return a;
}
static __device__ __forceinline__ void ldsm4(uint32_t* r, uint32_t addr) {
    asm volatile("ldmatrix.sync.aligned.m8n8.x4.shared.b16 {%0,%1,%2,%3}, [%4];"
                 : "=r"(r[0]), "=r"(r[1]), "=r"(r[2]), "=r"(r[3]) : "r"(addr));
}
static __device__ __forceinline__ void mma16816(float* d, const uint32_t* a, const uint32_t* b) {
    asm volatile(
        "mma.sync.aligned.m16n8k16.row.col.f32.f16.f16.f32 "
        "{%0,%1,%2,%3}, {%4,%5,%6,%7}, {%8,%9}, {%0,%1,%2,%3};"
        : "+f"(d[0]), "+f"(d[1]), "+f"(d[2]), "+f"(d[3])
        : "r"(a[0]), "r"(a[1]), "r"(a[2]), "r"(a[3]), "r"(b[0]), "r"(b[1]));
}
static __device__ __forceinline__ void cpa16(uint32_t dst, const void* src) {
    asm volatile("cp.async.cg.shared.global [%0], [%1], 16;" :: "r"(dst), "l"(src) : "memory");
}
#define CP_COMMIT_WAIT() \
    asm volatile("cp.async.commit_group;\ncp.async.wait_group 0;" ::: "memory")

static __device__ __forceinline__ uint32_t swz(uint32_t r, uint32_t c2) {
    return r * 256 + (c2 ^ ((r & 7) << 4));
}

// Dekker split of 4 floats into fp16 hi/lo packed words (~22-bit effective mantissa)
static __device__ __forceinline__ void split4h(float4 v, uint2& hi, uint2& lo) {
    __half h0 = __float2half(v.x), h1 = __float2half(v.y);
    __half h2 = __float2half(v.z), h3 = __float2half(v.w);
    __half l0 = __float2half(v.x - __half2float(h0));
    __half l1 = __float2half(v.y - __half2float(h1));
    __half l2 = __float2half(v.z - __half2float(h2));
    __half l3 = __float2half(v.w - __half2float(h3));
    hi.x = (uint32_t)__half_as_ushort(h0) | ((uint32_t)__half_as_ushort(h1) << 16);
    hi.y = (uint32_t)__half_as_ushort(h2) | ((uint32_t)__half_as_ushort(h3) << 16);
    lo.x = (uint32_t)__half_as_ushort(l0) | ((uint32_t)__half_as_ushort(l1) << 16);
    lo.y = (uint32_t)__half_as_ushort(l2) | ((uint32_t)__half_as_ushort(l3) << 16);
}

static __device__ __forceinline__ float sigf(float x) { return 1.f / (1.f + __expf(-x)); }

// edge-index dtype probe (int64 vs int32)
static __device__ __forceinline__ void edge_pair(const void* ei_raw, int e, int& src, int& dst) {
    const long long* e64 = (const long long*)ei_raw;
    bool is64 = (((unsigned long long)e64[0] < (unsigned long long)NN) &&
                 ((unsigned long long)e64[1] < (unsigned long long)NN));
    if (is64) {
        src = (int)e64[e];
        dst = (int)e64[EE + e];
    } else {
        const int* e32 = (const int*)ei_raw;
        src = e32[e];
        dst = e32[EE + e];
    }
}

// ---------------- prepass: Wfused + weight conversion ----------------
__global__ void wfused_kernel(const float* __restrict__ Wih, const float* __restrict__ Wconv) {
    int i = blockIdx.x * blockDim.x + threadIdx.x;
    if (i >= 3 * 384 * 128) return;
    int l = i / (384 * 128), r = (i >> 7) % 384, k = i & 127;
    const float* wc = Wconv + (size_t)l * 128 * 128;
    float s = 0.f;
#pragma unroll 8
    for (int j = 0; j < 128; j++) s = fmaf(__ldg(Wih + r * 128 + j), __ldg(wc + j * 128 + k), s);
    g_wf[i] = s;
}

// rows: [0,128) W1; [128,512) Whh; [512,896) W2; [896,2048) Wfused
__global__ void convert_w(const float* __restrict__ W1, const float* __restrict__ Whh,
                          const float* __restrict__ W2) {
    int i = blockIdx.x * blockDim.x + threadIdx.x;
    if (i >= 2048 * 128) return;
    int row = i >> 7, k = i & 127;
    float v;
    if (row < 128)       v = W1[(size_t)row * 128 + k];
    else if (row < 512)  v = Whh[(size_t)(row - 128) * 128 + k];
    else if (row < 896)  v = W2[(size_t)(row - 512) * 128 + k];
    else                 v = g_wf[(size_t)(row - 896) * 128 + k];
    int tile = row >> 7, tr = row & 127;
    uint32_t o = swz((uint32_t)tr, (uint32_t)(2 * k));
    *(__half*)((char*)g_wh + (size_t)tile * 32768 + o) = __float2half(v);
}

// ---------------- CSR build (once per launch) ----------------
__global__ void zero_deg() {
    int i = blockIdx.x * blockDim.x + threadIdx.x;
    if (i < NN) g_deg[i] = 0;
}
__global__ void count_kernel(const void* __restrict__ ei_raw) {
    int e = blockIdx.x * blockDim.x + threadIdx.x;
    if (e >= EE) return;
    int src, dst;
    edge_pair(ei_raw, e, src, dst);
    atomicAdd(&g_deg[dst], 1);
}
__global__ void scan1() {
    __shared__ int s[256];
    int i = blockIdx.x * 256 + threadIdx.x;
    int tid = threadIdx.x;
    int v = (i < NN) ? g_deg[i] : 0;
    s[tid] = v;
    __syncthreads();
    for (int d = 1; d < 256; d <<= 1) {
        int t = (tid >= d) ? s[tid - d] : 0;
        __syncthreads();
        s[tid] += t;
        __syncthreads();
    }
    if (i < NN) g_off[i] = s[tid] - v;
    if (tid == 255) g_bsum[blockIdx.x] = s[255];
}
__global__ void scan2() {
    __shared__ int s[512];
    int tid = threadIdx.x;
    int v = (tid < NB_SCAN) ? g_bsum[tid] : 0;
    s[tid] = v;
    __syncthreads();
    for (int d = 1; d < 512; d <<= 1) {
        int t = (tid >= d) ? s[tid - d] : 0;
        __syncthreads();
        s[tid] += t;
        __syncthreads();
    }
    if (tid < NB_SCAN) g_bsum2[tid] = s[tid] - v;
}
__global__ void scan3() {
    int i = blockIdx.x * 256 + threadIdx.x;
    if (i >= NN) return;
    int o = g_off[i] + g_bsum2[blockIdx.x];
    g_off[i] = o;
    g_pos[i] = o;
}
__global__ void fill_kernel(const void* __restrict__ ei_raw) {
    int e = blockIdx.x * blockDim.x + threadIdx.x;
    if (e >= EE) return;
    int src, dst;
    edge_pair(ei_raw, e, src, dst);
    int p = atomicAdd(&g_pos[dst], 1);
    g_csr[p] = src;
}

// ---------------- per-layer aggregation: warp-per-node CSR gather ----------------
__global__ void gather_agg(const __half2* __restrict__ h16, float* __restrict__ agg) {
    int t = blockIdx.x * blockDim.x + threadIdx.x;
    int n = t >> 5;
    int lane = t & 31;
    if (n >= NN) return;
    int e0 = g_off[n];
    int e1 = (n + 1 < NN) ? g_off[n + 1] : EE;
    float4 acc = make_float4(0.f, 0.f, 0.f, 0.f);
    int e = e0;
    for (; e + 1 < e1; e += 2) {
        int s0 = g_csr[e], s1 = g_csr[e + 1];
        const __half2* p0 = h16 + (size_t)s0 * 64 + lane * 2;
        const __half2* p1 = h16 + (size_t)s1 * 64 + lane * 2;
        float2 a0 = __half22float2(p0[0]), b0 = __half22float2(p0[1]);
        float2 a1 = __half22float2(p1[0]), b1 = __half22float2(p1[1]);
        acc.x += a0.x + a1.x;
        acc.y += a0.y + a1.y;
        acc.z += b0.x + b1.x;
        acc.w += b0.y + b1.y;
    }
    if (e < e1) {
        int s0 = g_csr[e];
        const __half2* p0 = h16 + (size_t)s0 * 64 + lane * 2;
        float2 a0 = __half22float2(p0[0]), b0 = __half22float2(p0[1]);
        acc.x += a0.x; acc.y += a0.y; acc.z += b0.x; acc.w += b0.y;
    }
    *(float4*)(agg + (size_t)n * DD + lane * 4) = acc;
}

// SMEM: A hi/lo (64x128 = 16KB each), B (128x128 = 32KB) = 64KB -> occ 3
#define SM_A_HI 0
#define SM_A_LO 16384
#define SM_B 32768
#define SM_TOTAL 65536

// ---------------- shared GEMM body ----------------
// Tile 64(M) x 128(N), 8 warps; PASSES=2: A fp32 Dekker hi/lo; PASSES=1: A fp16 direct.
// Output fp16 (half2 stores), bias always on, no activations.
template <int PASSES, int MT>
static __device__ __forceinline__ void gemm_body(
    const void* __restrict__ Asrc, int wtile0,
    const float* __restrict__ bias, __half2* __restrict__ C, char* smem) {
    const uint32_t sb = smem_u32(smem);
    const int tid = threadIdx.x, lane = tid & 31, wid = tid >> 5;
    const int warp_m = (wid & 1) * 32;
    const int warp_n = (wid >> 1) * 32;
    const int n0 = blockIdx.x * 64;

    const int a_row = lane & 15;
    const int a_kh = (lane >> 4) & 1;
    const int b_row = (lane & 7) | (((lane >> 4) & 1) << 3);
    const int b_kh = (lane >> 3) & 1;

    // ---- fill A tile ----
    if (PASSES == 2) {
        const float* A = (const float*)Asrc;
        for (int i = tid; i < 2048; i += 256) {
            int r = i >> 5, k = (i & 31) << 2;
            int gr = n0 + r;
            if (gr >= NN) gr = NN - 1;
            float4 v = *(const float4*)(A + (size_t)gr * 128 + k);
            uint2 hi, lo;
            split4h(v, hi, lo);
            uint32_t o = swz((uint32_t)r, (uint32_t)(k * 2));
            *(uint2*)(smem + SM_A_HI + o) = hi;
            *(uint2*)(smem + SM_A_LO + o) = lo;
        }
    } else {
        const __half* A = (const __half*)Asrc;
        for (int i = tid; i < 2048; i += 256) {
            int r = i >> 5, k = (i & 31) << 2;
            int gr = n0 + r;
            if (gr >= NN) gr = NN - 1;
            uint2 hv = *(const uint2*)(A + (size_t)gr * 128 + k);  // 4 halves
            *(uint2*)(smem + SM_A_HI + swz((uint32_t)r, (uint32_t)(k * 2))) = hv;
        }
    }

    for (int mt = 0; mt < MT; mt++) {
        const char* wb = (const char*)g_wh + (size_t)(wtile0 + mt) * 32768;
        for (int i = tid; i < 2048; i += 256) {
            cpa16(sb + SM_B + i * 16, wb + i * 16);
        }
        CP_COMMIT_WAIT();
        __syncthreads();

        float acc[2][4][4];
#pragma unroll
        for (int t = 0; t < 2; t++)
#pragma unroll
            for (int u = 0; u < 4; u++)
#pragma unroll
                for (int q = 0; q < 4; q++) acc[t][u][q] = 0.f;

#pragma unroll 1
        for (int p = 0; p < PASSES; p++) {
            const uint32_t Ab = sb + (p ? SM_A_LO : SM_A_HI);
#pragma unroll
            for (int ks = 0; ks < 8; ks++) {
                const uint32_t c2a = ks * 32 + a_kh * 16;
                const uint32_t c2b = ks * 32 + b_kh * 16;
                uint32_t afr[2][4], bfr[4][2];
#pragma unroll
                for (int t = 0; t < 2; t++)
                    ldsm4(afr[t], Ab + swz(warp_m + t * 16 + a_row, c2a));
#pragma unroll
                for (int ub = 0; ub < 2; ub++) {
                    uint32_t tmp[4];
                    ldsm4(tmp, sb + SM_B + swz(warp_n + ub * 16 + b_row, c2b));
                    bfr[2 * ub][0] = tmp[0]; bfr[2 * ub][1] = tmp[1];
                    bfr[2 * ub + 1][0] = tmp[2]; bfr[2 * ub + 1][1] = tmp[3];
                }
#pragma unroll
                for (int t = 0; t < 2; t++)
#pragma unroll
                    for (int u = 0; u < 4; u++)
                        mma16816(acc[t][u], afr[t], bfr[u]);
            }
        }

        // ---- epilogue: bias + fp16 stores ----
        const int M = MT * 128;
        const int row0 = n0 + warp_m + (lane >> 2);
        const int colb = mt * 128 + warp_n + (lane & 3) * 2;
#pragma unroll
        for (int u = 0; u < 4; u++) {
            const int c = colb + u * 8;
            float b0 = __ldg(bias + c), b1 = __ldg(bias + c + 1);
#pragma unroll
            for (int t = 0; t < 2; t++) {
                const int r = row0 + t * 16;
                if (r < NN)
                    C[((size_t)r * M + c) >> 1] =
                        __floats2half2_rn(acc[t][u][0] + b0, acc[t][u][1] + b1);
                if (r + 8 < NN)
                    C[((size_t)(r + 8) * M + c) >> 1] =
                        __floats2half2_rn(acc[t][u][2] + b0, acc[t][u][3] + b1);
            }
        }
        if (MT > 1) __syncthreads();
    }
}

// dual GEMM: y=0 -> gi = agg @ Wfused[l]^T + bih (2-pass fp32 A)
//            y=1 -> gh = h16 @ Whh^T + bhh      (1-pass fp16 A)
__global__ __launch_bounds__(256, 3)
void dual_gemm(const float* __restrict__ agg, const __half* __restrict__ h16,
               int wt_gi, const float* __restrict__ bih, const float* __restrict__ bhh,
               __half2* __restrict__ gi, __half2* __restrict__ gh) {
    extern __shared__ char smem[];
    if (blockIdx.y == 0)
        gemm_body<2, 3>(agg, wt_gi, bih, gi, smem);
    else
        gemm_body<1, 3>(h16, 1, bhh, gh, smem);
}

// ======== standalone GEMM (linear1 / linear2): fp32 A 2-pass, fp32 C ========
// OUTH: 0 = fp32 C only, 2 = fp32 C + fp16 copy to C2.
template <int ACTIN, int ACTOUT, int MT, int OUTH>
__global__ __launch_bounds__(256, 3)
void gemm_mma(const float* __restrict__ A, int wtile0,
              const float* __restrict__ bias, float* __restrict__ C,
              __half* __restrict__ C2) {
    extern __shared__ char smem[];
    const uint32_t sb = smem_u32(smem);
    const int tid = threadIdx.x, lane = tid & 31, wid = tid >> 5;
    const int warp_m = (wid & 1) * 32;
    const int warp_n = (wid >> 1) * 32;
    const int n0 = blockIdx.x * 64;

    const int a_row = lane & 15;
    const int a_kh = (lane >> 4) & 1;
    const int b_row = (lane & 7) | (((lane >> 4) & 1) << 3);
    const int b_kh = (lane >> 3) & 1;

    for (int i = tid; i < 2048; i += 256) {
        int r = i >> 5, k = (i & 31) << 2;
        int gr = n0 + r;
        if (gr >= NN) gr = NN - 1;
        float4 v = *(const float4*)(A + (size_t)gr * 128 + k);
        if (ACTIN) {
            v.x = fmaxf(v.x, 0.f); v.y = fmaxf(v.y, 0.f);
            v.z = fmaxf(v.z, 0.f); v.w = fmaxf(v.w, 0.f);
        }
        uint2 hi, lo;
        split4h(v, hi, lo);
        uint32_t o = swz((uint32_t)r, (uint32_t)(k * 2));
        *(uint2*)(smem + SM_A_HI + o) = hi;
        *(uint2*)(smem + SM_A_LO + o) = lo;
    }

    for (int mt = 0; mt < MT; mt++) {
        const char* wb = (const char*)g_wh + (size_t)(wtile0 + mt) * 32768;
        for (int i = tid; i < 2048; i += 256) {
            cpa16(sb + SM_B + i * 16, wb + i * 16);
        }
        CP_COMMIT_WAIT();
        __syncthreads();

        float acc[2][4][4];
#pragma unroll
        for (int t = 0; t < 2; t++)
#pragma unroll
            for (int u = 0; u < 4; u++)
#pragma unroll
                for (int q = 0; q < 4; q++) acc[t][u][q] = 0.f;

#pragma unroll 1
        for (int p = 0; p < 2; p++) {
            const uint32_t Ab = sb + (p ? SM_A_LO : SM_A_HI);
#pragma unroll
            for (int ks = 0; ks < 8; ks++) {
                const uint32_t c2a = ks * 32 + a_kh * 16;
                const uint32_t c2b = ks * 32 + b_kh * 16;
                uint32_t afr[2][4], bfr[4][2];
#pragma unroll
                for (int t = 0; t < 2; t++)
                    ldsm4(afr[t], Ab + swz(warp_m + t * 16 + a_row, c2a));
#pragma unroll
                for (int ub = 0; ub < 2; ub++) {
                    uint32_t tmp[4];
                    ldsm4(tmp, sb + SM_B + swz(warp_n + ub * 16 + b_row, c2b));
                    bfr[2 * ub][0] = tmp[0]; bfr[2 * ub][1] = tmp[1];
                    bfr[2 * ub + 1][0] = tmp[2]; bfr[2 * ub + 1][1] = tmp[3];
                }
#pragma unroll
                for (int t = 0; t < 2; t++)
#pragma unroll
                    for (int u = 0; u < 4; u++)
                        mma16816(acc[t][u], afr[t], bfr[u]);
            }
        }

        const int M = MT * 128;
        const int row0 = n0 + warp_m + (lane >> 2);
        const int colb = mt * 128 + warp_n + (lane & 3) * 2;
#pragma unroll
        for (int u = 0; u < 4; u++) {
            const int c = colb + u * 8;
            float b0 = __ldg(bias + c), b1 = __ldg(bias + c + 1);
#pragma unroll
            for (int t = 0; t < 2; t++) {
                const int r = row0 + t * 16;
                float v0 = acc[t][u][0] + b0, v1 = acc[t][u][1] + b1;
                float v2 = acc[t][u][2] + b0, v3 = acc[t][u][3] + b1;
                if (ACTOUT) {
                    v0 = fmaxf(v0, 0.f); v1 = fmaxf(v1, 0.f);
                    v2 = fmaxf(v2, 0.f); v3 = fmaxf(v3, 0.f);
                }
                if (r < NN) {
                    *(float2*)(C + (size_t)r * M + c) = make_float2(v0, v1);
                    if (OUTH == 2)
                        *(__half2*)(C2 + (size_t)r * M + c) = __floats2half2_rn(v0, v1);
                }
                if (r + 8 < NN) {
                    *(float2*)(C + (size_t)(r + 8) * M + c) = make_float2(v2, v3);
                    if (OUTH == 2)
                        *(__half2*)(C2 + (size_t)(r + 8) * M + c) = __floats2half2_rn(v2, v3);
                }
            }
        }
        if (MT > 1) __syncthreads();
    }
}

// ---------------- GRU gate fusion (fp16 gi/gh; writes h fp32 + h16 fp16) ----------------
static __device__ __forceinline__ float gate1(float ir, float iz, float in_,
                                              float hr, float hz, float hn, float hv) {
    float r = sigf(ir + hr);
    float z = sigf(iz + hz);
    float n = tanhf(in_ + r * hn);
    return (1.f - z) * n + z * hv;
}

__global__ void gru_gate(const __half2* __restrict__ gi, const __half2* __restrict__ gh,
                         float* __restrict__ h, __half2* __restrict__ h16) {
    int t = blockIdx.x * blockDim.x + threadIdx.x;
    int n = t >> 5;
    int d4 = (t & 31) << 2;
    if (n >= NN) return;
    size_t bi = ((size_t)n * 384 + d4) >> 1;
    float2 ir01 = __half22float2(gi[bi]),       ir23 = __half22float2(gi[bi + 1]);
    float2 iz01 = __half22float2(gi[bi + 64]),  iz23 = __half22float2(gi[bi + 65]);
    float2 in01 = __half22float2(gi[bi + 128]), in23 = __half22float2(gi[bi + 129]);
    float2 hr01 = __half22float2(gh[bi]),       hr23 = __half22float2(gh[bi + 1]);
    float2 hz01 = __half22float2(gh[bi + 64]),  hz23 = __half22float2(gh[bi + 65]);
    float2 hn01 = __half22float2(gh[bi + 128]), hn23 = __half22float2(gh[bi + 129]);
    float4* hp = (float4*)(h + (size_t)n * 128 + d4);
    float4 hv = *hp;
    float4 o;
    o.x = gate1(ir01.x, iz01.x, in01.x, hr01.x, hz01.x, hn01.x, hv.x);
    o.y = gate1(ir01.y, iz01.y, in01.y, hr01.y, hz01.y, hn01.y, hv.y);
    o.z = gate1(ir23.x, iz23.x, in23.x, hr23.x, hz23.x, hn23.x, hv.z);
    o.w = gate1(ir23.y, iz23.y, in23.y, hr23.y, hz23.y, hn23.y, hv.w);
    *hp = o;
    size_t hi2 = ((size_t)n * 128 + d4) >> 1;
    h16[hi2] = __floats2half2_rn(o.x, o.y);
    h16[hi2 + 1] = __floats2half2_rn(o.z, o.w);
}

// ---------------- launcher ----------------
extern "C" void kernel_launch(void* const* d_in, const int* in_sizes, int n_in,
                              void* d_out, int out_size) {
    const float* x     = (const float*)d_in[0];
    const void*  ei    = (const void*)d_in[1];
    const float* W1    = (const float*)d_in[2];
    const float* b1    = (const float*)d_in[3];
    const float* Wconv = (const float*)d_in[4];
    const float* Wih   = (const float*)d_in[5];
    const float* Whh   = (const float*)d_in[6];
    const float* bih   = (const float*)d_in[7];
    const float* bhh   = (const float*)d_in[8];
    const float* W2    = (const float*)d_in[9];
    const float* b2    = (const float*)d_in[10];
    float* out = (float*)d_out;

    float *h, *agg;
    __half *h16, *gi, *gh;
    cudaGetSymbolAddress((void**)&h, g_h);
    cudaGetSymbolAddress((void**)&h16, g_h16);
    cudaGetSymbolAddress((void**)&agg, g_agg);
    cudaGetSymbolAddress((void**)&gi, g_gi);
    cudaGetSymbolAddress((void**)&gh, g_gh);

    cudaFuncSetAttribute(gemm_mma<0, 1, 1, 2>, cudaFuncAttributeMaxDynamicSharedMemorySize, SM_TOTAL);
    cudaFuncSetAttribute(gemm_mma<1, 0, 3, 0>, cudaFuncAttributeMaxDynamicSharedMemorySize, SM_TOTAL);
    cudaFuncSetAttribute(dual_gemm, cudaFuncAttributeMaxDynamicSharedMemorySize, SM_TOTAL);

    // side stream for the CSR prepass (capture-legal fork)
    cudaStream_t s2;
    cudaStreamCreateWithFlags(&s2, cudaStreamNonBlocking);
    cudaEvent_t evFork, evCSR;
    cudaEventCreateWithFlags(&evFork, cudaEventDisableTiming);
    cudaEventCreateWithFlags(&evCSR, cudaEventDisableTiming);
    cudaEventRecord(evFork, 0);
    cudaStreamWaitEvent(s2, evFork, 0);

    // CSR build on s2 (overlaps weight prep + linear1 on main)
    zero_deg<<<NB_SCAN, 256, 0, s2>>>();
    count_kernel<<<(EE + 255) / 256, 256, 0, s2>>>(ei);
    scan1<<<NB_SCAN, 256, 0, s2>>>();
    scan2<<<1, 512, 0, s2>>>();
    scan3<<<NB_SCAN, 256, 0, s2>>>();
    fill_kernel<<<(EE + 255) / 256, 256, 0, s2>>>(ei);
    cudaEventRecord(evCSR, s2);

    // weight prepasses (main stream)
    wfused_kernel<<<(3 * 384 * 128 + 255) / 256, 256>>>(Wih, Wconv);
    convert_w<<<(2048 * 128 + 255) / 256, 256>>>(W1, Whh, W2);

    // h = relu(x @ W1^T + b1), fp32 + fp16 copies
    gemm_mma<0, 1, 1, 2><<<NT64, 256, SM_TOTAL>>>(x, 0, b1, h, h16);

    cudaStreamWaitEvent(0, evCSR, 0);  // CSR ready before first gather

    for (int l = 0; l < 3; l++) {
        // agg = CSR-gather(h16)
        gather_agg<<<(NN * 32 + 255) / 256, 256>>>((const __half2*)h16, agg);
        // gi = agg @ Wfused[l]^T + bih ; gh = h16 @ Whh^T + bhh  (one launch)
        dual_gemm<<<dim3(NT64, 2), 256, SM_TOTAL>>>(agg, h16, 7 + 3 * l, bih, bhh,
                                                    (__half2*)gi, (__half2*)gh);
        // h = GRU(gi, gh) -> h fp32 + h16
        gru_gate<<<NN * 32 / 256, 256>>>((const __half2*)gi, (const __half2*)gh, h, (__half2*)h16);
    }

    // out = relu(h) @ W2^T + b2
    gemm_mma<1, 0, 3, 0><<<NT64, 256, SM_TOTAL>>>(h, 4, b2, out, nullptr);

    cudaEventDestroy(evFork);
    cudaEventDestroy(evCSR);
    cudaStreamDestroy(s2);
}